// round 8
// baseline (speedup 1.0000x reference)
#include <cuda_runtime.h>
#include <cstdint>
#include <cstddef>

#define BB 8
#define TT 2048
#define FF 128
#define NT 256   // num tatums

// ---------------- scratch (device globals; no allocs allowed) ----------------
__device__ float g_x0[(size_t)BB * 2 * TT * FF];        // 16.8 MB
__device__ float g_a [(size_t)BB * 32 * TT * FF];       // 268 MB
__device__ float g_b [(size_t)BB * 32 * TT * FF];       // 268 MB

// ---------------- gather: build (B,2,T,F) input ----------------
// tatum_frames may be int32 or int64 (jax x64 ambiguity). Detect on device:
// as-int32 index 513: int32 layout -> tf[1][256] = 2048 (nonzero);
// int64 layout -> high word of tf[0][256] = 0. Values <= 2048, so low words exact.
__global__ void gather_kernel(const float* __restrict__ pitch,
                              const float* __restrict__ onset,
                              const int*   __restrict__ tf32,
                              float* __restrict__ x0)
{
    const int t = blockIdx.x;
    const int b = blockIdx.y;
    const int f = threadIdx.x;           // 128 threads

    const int stride = (tf32[513] == 0) ? 2 : 1;
    const int* row = tf32 + (size_t)b * (NT + 1) * stride;

    // first j in [1, 257) with row[j] > t  ->  count = j-1
    int lo = 1, hi = NT + 1;
    while (lo < hi) {
        int mid = (lo + hi) >> 1;
        if (row[(size_t)mid * stride] <= t) lo = mid + 1; else hi = mid;
    }
    int idx = lo - 1;
    if (idx > NT - 1) idx = NT - 1;
    const bool valid = t < row[(size_t)NT * stride];

    const float pv = valid ? pitch[((size_t)b * NT + idx) * FF + f] : 0.f;
    const float ov = valid ? onset[(size_t)b * NT + idx] : 0.f;

    const size_t base = ((size_t)b * 2 * TT + t) * FF + f;
    x0[base] = pv;
    x0[base + (size_t)TT * FF] = ov;
}

// ---------------- 3x3 SAME conv, COUT=32, register-tiled ----------------
// block: 256 thr = 8 cout-groups x 32 f-lanes; thread: 4 couts x 8 t-rows.
// smem: xs[CIN][10][34] (t0-1..t0+8, f0-1..f0+32), ws[(tap*CIN+cin)*32+cout]
template<int CIN, bool RELU>
__global__ __launch_bounds__(256, 2)
void conv3x3(const float* __restrict__ in,
             const float* __restrict__ Wg,    // OIHW [32][CIN][3][3]
             const float* __restrict__ bg,    // [32]
             float* __restrict__ out)         // (B,32,T,F)
{
    extern __shared__ float sm[];
    float* xs = sm;                     // CIN*340
    float* ws = sm + CIN * 340;         // 9*CIN*32

    const int tid  = threadIdx.x;
    const int lane = tid & 31;          // f offset
    const int cg   = tid >> 5;          // cout group 0..7
    const int f0   = blockIdx.x * 32;
    const int t0   = blockIdx.y * 8;
    const int b    = blockIdx.z;

    // weights: OIHW -> [tap][cin][cout]
    for (int i = tid; i < 9 * CIN * 32; i += 256) {
        int cout = i / (CIN * 9);
        int r    = i - cout * CIN * 9;
        int cin  = r / 9;
        int tap  = r - cin * 9;
        ws[(tap * CIN + cin) * 32 + cout] = Wg[i];
    }
    // input tile with zero halo
    const float* inb = in + (size_t)b * CIN * TT * FF;
    for (int i = tid; i < CIN * 340; i += 256) {
        int cin = i / 340;
        int r   = i - cin * 340;
        int tt  = r / 34;
        int ff  = r - tt * 34;
        int gt  = t0 - 1 + tt;
        int gf  = f0 - 1 + ff;
        float v = 0.f;
        if ((unsigned)gt < (unsigned)TT && (unsigned)gf < (unsigned)FF)
            v = inb[((size_t)cin * TT + gt) * FF + gf];
        xs[i] = v;
    }
    __syncthreads();

    float acc[4][8];
    {
        const float4 bv = *(const float4*)(bg + cg * 4);
        #pragma unroll
        for (int p = 0; p < 8; p++) {
            acc[0][p] = bv.x; acc[1][p] = bv.y; acc[2][p] = bv.z; acc[3][p] = bv.w;
        }
    }

    #pragma unroll
    for (int tap = 0; tap < 9; tap++) {
        const int ky = tap / 3, kx = tap % 3;
        const float* xbase = xs + ky * 34 + kx + lane;
        const float* wbase = ws + tap * CIN * 32 + cg * 4;
        #pragma unroll 4
        for (int cin = 0; cin < CIN; ++cin) {
            const float4 w4 = *(const float4*)(wbase + cin * 32);
            const float* xp = xbase + cin * 340;
            #pragma unroll
            for (int p = 0; p < 8; p++) {
                const float xv = xp[p * 34];
                acc[0][p] = fmaf(w4.x, xv, acc[0][p]);
                acc[1][p] = fmaf(w4.y, xv, acc[1][p]);
                acc[2][p] = fmaf(w4.z, xv, acc[2][p]);
                acc[3][p] = fmaf(w4.w, xv, acc[3][p]);
            }
        }
    }

    float* ob = out + (size_t)b * 32 * TT * FF;
    #pragma unroll
    for (int j = 0; j < 4; j++) {
        const int cout = cg * 4 + j;
        #pragma unroll
        for (int p = 0; p < 8; p++) {
            float v = acc[j][p];
            if (RELU) v = fmaxf(v, 0.f);
            ob[((size_t)cout * TT + (t0 + p)) * FF + f0 + lane] = v;
        }
    }
}

// ---------------- final 3x3 conv, CIN=32 -> COUT=1, no relu ----------------
__global__ __launch_bounds__(256, 2)
void conv3x3_out(const float* __restrict__ in,   // (B,32,T,F)
                 const float* __restrict__ Wg,   // [1][32][3][3]
                 const float* __restrict__ bg,   // [1]
                 float* __restrict__ out)        // (B,T,F)
{
    extern __shared__ float sm[];
    float* xs = sm;                // 32*340
    float* ws = sm + 32 * 340;     // [tap][cin] 288

    const int tid  = threadIdx.x;
    const int lane = tid & 31;     // f offset
    const int pr   = tid >> 5;     // t row 0..7
    const int f0   = blockIdx.x * 32;
    const int t0   = blockIdx.y * 8;
    const int b    = blockIdx.z;

    for (int i = tid; i < 288; i += 256) {
        int cin = i / 9;
        int tap = i - cin * 9;
        ws[tap * 32 + cin] = Wg[i];
    }
    const float* inb = in + (size_t)b * 32 * TT * FF;
    for (int i = tid; i < 32 * 340; i += 256) {
        int cin = i / 340;
        int r   = i - cin * 340;
        int tt  = r / 34;
        int ff  = r - tt * 34;
        int gt  = t0 - 1 + tt;
        int gf  = f0 - 1 + ff;
        float v = 0.f;
        if ((unsigned)gt < (unsigned)TT && (unsigned)gf < (unsigned)FF)
            v = inb[((size_t)cin * TT + gt) * FF + gf];
        xs[i] = v;
    }
    __syncthreads();

    float acc = bg[0];
    #pragma unroll
    for (int tap = 0; tap < 9; tap++) {
        const int ky = tap / 3, kx = tap % 3;
        const float* xp = xs + (pr + ky) * 34 + kx + lane;
        const float* wp = ws + tap * 32;
        #pragma unroll
        for (int cin = 0; cin < 32; cin += 4) {
            const float4 w4 = *(const float4*)(wp + cin);
            acc = fmaf(w4.x, xp[(cin + 0) * 340], acc);
            acc = fmaf(w4.y, xp[(cin + 1) * 340], acc);
            acc = fmaf(w4.z, xp[(cin + 2) * 340], acc);
            acc = fmaf(w4.w, xp[(cin + 3) * 340], acc);
        }
    }
    out[((size_t)b * TT + (t0 + pr)) * FF + f0 + lane] = acc;
}

// ---------------- launch ----------------
extern "C" void kernel_launch(void* const* d_in, const int* in_sizes, int n_in,
                              void* d_out, int out_size)
{
    const float* pitch = (const float*)d_in[0];
    const float* onset = (const float*)d_in[1];
    const int*   tf    = (const int*)  d_in[2];
    const float* W1 = (const float*)d_in[3];  const float* b1 = (const float*)d_in[4];
    const float* W2 = (const float*)d_in[5];  const float* b2 = (const float*)d_in[6];
    const float* W3 = (const float*)d_in[7];  const float* b3 = (const float*)d_in[8];
    const float* W4 = (const float*)d_in[9];  const float* b4 = (const float*)d_in[10];
    float* out = (float*)d_out;

    float *x0, *a, *buf;
    cudaGetSymbolAddress((void**)&x0,  g_x0);
    cudaGetSymbolAddress((void**)&a,   g_a);
    cudaGetSymbolAddress((void**)&buf, g_b);

    const size_t sm2  = (size_t)(2  * 340 + 9 * 2  * 32) * 4;   //  5.0 KB
    const size_t sm32 = (size_t)(32 * 340 + 9 * 32 * 32) * 4;   // 80.4 KB
    const size_t smo  = (size_t)(32 * 340 + 288) * 4;           // 44.7 KB

    cudaFuncSetAttribute(conv3x3<32, true>, cudaFuncAttributeMaxDynamicSharedMemorySize, (int)sm32);
    cudaFuncSetAttribute(conv3x3_out,       cudaFuncAttributeMaxDynamicSharedMemorySize, (int)smo);

    gather_kernel<<<dim3(TT, BB), 128>>>(pitch, onset, tf, x0);

    dim3 grid(FF / 32, TT / 8, BB);
    conv3x3<2,  true><<<grid, 256, sm2 >>>(x0,  W1, b1, a);
    conv3x3<32, true><<<grid, 256, sm32>>>(a,   W2, b2, buf);
    conv3x3<32, true><<<grid, 256, sm32>>>(buf, W3, b3, a);
    conv3x3_out      <<<grid, 256, smo >>>(a,   W4, b4, out);
}

// round 9
// speedup vs baseline: 1.0045x; 1.0045x over previous
#include <cuda_runtime.h>
#include <cstdint>
#include <cstddef>

#define BB 8
#define TT 2048
#define FF 128
#define NT 256   // num tatums

// ---------------- scratch (device globals; no allocs allowed) ----------------
__device__ float g_x0[(size_t)BB * 2 * TT * FF];        // 16.8 MB
__device__ float g_a [(size_t)BB * 32 * TT * FF];       // 268 MB
__device__ float g_b [(size_t)BB * 32 * TT * FF];       // 268 MB

// ---------------- gather: build (B,2,T,F) input ----------------
// tatum_frames may be int32 or int64 (jax x64 ambiguity). Detect on device:
// as-int32 index 513: int32 layout -> tf[1][256] = 2048 (nonzero);
// int64 layout -> high word of tf[0][256] = 0. Values <= 2048, so low words exact.
__global__ void gather_kernel(const float* __restrict__ pitch,
                              const float* __restrict__ onset,
                              const int*   __restrict__ tf32,
                              float* __restrict__ x0)
{
    const int t = blockIdx.x;
    const int b = blockIdx.y;
    const int f = threadIdx.x;           // 128 threads

    const int stride = (tf32[513] == 0) ? 2 : 1;
    const int* row = tf32 + (size_t)b * (NT + 1) * stride;

    // first j in [1, 257) with row[j] > t  ->  count = j-1
    int lo = 1, hi = NT + 1;
    while (lo < hi) {
        int mid = (lo + hi) >> 1;
        if (row[(size_t)mid * stride] <= t) lo = mid + 1; else hi = mid;
    }
    int idx = lo - 1;
    if (idx > NT - 1) idx = NT - 1;
    const bool valid = t < row[(size_t)NT * stride];

    const float pv = valid ? pitch[((size_t)b * NT + idx) * FF + f] : 0.f;
    const float ov = valid ? onset[(size_t)b * NT + idx] : 0.f;

    const size_t base = ((size_t)b * 2 * TT + t) * FF + f;
    x0[base] = pv;
    x0[base + (size_t)TT * FF] = ov;
}

// ---------------- 3x3 SAME conv, COUT=32, register-tiled ----------------
// block: 256 thr = 8 cout-groups x 32 f-lanes; thread: 4 couts x 8 t-rows.
// smem: xs[CIN][10][34] (t0-1..t0+8, f0-1..f0+32), ws[(tap*CIN+cin)*32+cout]
template<int CIN, bool RELU>
__global__ __launch_bounds__(256, 2)
void conv3x3(const float* __restrict__ in,
             const float* __restrict__ Wg,    // OIHW [32][CIN][3][3]
             const float* __restrict__ bg,    // [32]
             float* __restrict__ out)         // (B,32,T,F)
{
    extern __shared__ float sm[];
    float* xs = sm;                     // CIN*340
    float* ws = sm + CIN * 340;         // 9*CIN*32

    const int tid  = threadIdx.x;
    const int lane = tid & 31;          // f offset
    const int cg   = tid >> 5;          // cout group 0..7
    const int f0   = blockIdx.x * 32;
    const int t0   = blockIdx.y * 8;
    const int b    = blockIdx.z;

    // weights: OIHW -> [tap][cin][cout]
    for (int i = tid; i < 9 * CIN * 32; i += 256) {
        int cout = i / (CIN * 9);
        int r    = i - cout * CIN * 9;
        int cin  = r / 9;
        int tap  = r - cin * 9;
        ws[(tap * CIN + cin) * 32 + cout] = Wg[i];
    }
    // input tile with zero halo
    const float* inb = in + (size_t)b * CIN * TT * FF;
    for (int i = tid; i < CIN * 340; i += 256) {
        int cin = i / 340;
        int r   = i - cin * 340;
        int tt  = r / 34;
        int ff  = r - tt * 34;
        int gt  = t0 - 1 + tt;
        int gf  = f0 - 1 + ff;
        float v = 0.f;
        if ((unsigned)gt < (unsigned)TT && (unsigned)gf < (unsigned)FF)
            v = inb[((size_t)cin * TT + gt) * FF + gf];
        xs[i] = v;
    }
    __syncthreads();

    float acc[4][8];
    {
        const float4 bv = *(const float4*)(bg + cg * 4);
        #pragma unroll
        for (int p = 0; p < 8; p++) {
            acc[0][p] = bv.x; acc[1][p] = bv.y; acc[2][p] = bv.z; acc[3][p] = bv.w;
        }
    }

    #pragma unroll
    for (int tap = 0; tap < 9; tap++) {
        const int ky = tap / 3, kx = tap % 3;
        const float* xbase = xs + ky * 34 + kx + lane;
        const float* wbase = ws + tap * CIN * 32 + cg * 4;
        #pragma unroll 4
        for (int cin = 0; cin < CIN; ++cin) {
            const float4 w4 = *(const float4*)(wbase + cin * 32);
            const float* xp = xbase + cin * 340;
            #pragma unroll
            for (int p = 0; p < 8; p++) {
                const float xv = xp[p * 34];
                acc[0][p] = fmaf(w4.x, xv, acc[0][p]);
                acc[1][p] = fmaf(w4.y, xv, acc[1][p]);
                acc[2][p] = fmaf(w4.z, xv, acc[2][p]);
                acc[3][p] = fmaf(w4.w, xv, acc[3][p]);
            }
        }
    }

    float* ob = out + (size_t)b * 32 * TT * FF;
    #pragma unroll
    for (int j = 0; j < 4; j++) {
        const int cout = cg * 4 + j;
        #pragma unroll
        for (int p = 0; p < 8; p++) {
            float v = acc[j][p];
            if (RELU) v = fmaxf(v, 0.f);
            ob[((size_t)cout * TT + (t0 + p)) * FF + f0 + lane] = v;
        }
    }
}

// ---------------- final 3x3 conv, CIN=32 -> COUT=1, no relu ----------------
__global__ __launch_bounds__(256, 2)
void conv3x3_out(const float* __restrict__ in,   // (B,32,T,F)
                 const float* __restrict__ Wg,   // [1][32][3][3]
                 const float* __restrict__ bg,   // [1]
                 float* __restrict__ out)        // (B,T,F)
{
    extern __shared__ float sm[];
    float* xs = sm;                // 32*340
    float* ws = sm + 32 * 340;     // [tap][cin] 288

    const int tid  = threadIdx.x;
    const int lane = tid & 31;     // f offset
    const int pr   = tid >> 5;     // t row 0..7
    const int f0   = blockIdx.x * 32;
    const int t0   = blockIdx.y * 8;
    const int b    = blockIdx.z;

    for (int i = tid; i < 288; i += 256) {
        int cin = i / 9;
        int tap = i - cin * 9;
        ws[tap * 32 + cin] = Wg[i];
    }
    const float* inb = in + (size_t)b * 32 * TT * FF;
    for (int i = tid; i < 32 * 340; i += 256) {
        int cin = i / 340;
        int r   = i - cin * 340;
        int tt  = r / 34;
        int ff  = r - tt * 34;
        int gt  = t0 - 1 + tt;
        int gf  = f0 - 1 + ff;
        float v = 0.f;
        if ((unsigned)gt < (unsigned)TT && (unsigned)gf < (unsigned)FF)
            v = inb[((size_t)cin * TT + gt) * FF + gf];
        xs[i] = v;
    }
    __syncthreads();

    float acc = bg[0];
    #pragma unroll
    for (int tap = 0; tap < 9; tap++) {
        const int ky = tap / 3, kx = tap % 3;
        const float* xp = xs + (pr + ky) * 34 + kx + lane;
        const float* wp = ws + tap * 32;
        #pragma unroll
        for (int cin = 0; cin < 32; cin += 4) {
            const float4 w4 = *(const float4*)(wp + cin);
            acc = fmaf(w4.x, xp[(cin + 0) * 340], acc);
            acc = fmaf(w4.y, xp[(cin + 1) * 340], acc);
            acc = fmaf(w4.z, xp[(cin + 2) * 340], acc);
            acc = fmaf(w4.w, xp[(cin + 3) * 340], acc);
        }
    }
    out[((size_t)b * TT + (t0 + pr)) * FF + f0 + lane] = acc;
}

// ---------------- launch ----------------
extern "C" void kernel_launch(void* const* d_in, const int* in_sizes, int n_in,
                              void* d_out, int out_size)
{
    const float* pitch = (const float*)d_in[0];
    const float* onset = (const float*)d_in[1];
    const int*   tf    = (const int*)  d_in[2];
    const float* W1 = (const float*)d_in[3];  const float* b1 = (const float*)d_in[4];
    const float* W2 = (const float*)d_in[5];  const float* b2 = (const float*)d_in[6];
    const float* W3 = (const float*)d_in[7];  const float* b3 = (const float*)d_in[8];
    const float* W4 = (const float*)d_in[9];  const float* b4 = (const float*)d_in[10];
    float* out = (float*)d_out;

    float *x0, *a, *buf;
    cudaGetSymbolAddress((void**)&x0,  g_x0);
    cudaGetSymbolAddress((void**)&a,   g_a);
    cudaGetSymbolAddress((void**)&buf, g_b);

    const size_t sm2  = (size_t)(2  * 340 + 9 * 2  * 32) * 4;   //  5.0 KB
    const size_t sm32 = (size_t)(32 * 340 + 9 * 32 * 32) * 4;   // 80.4 KB
    const size_t smo  = (size_t)(32 * 340 + 288) * 4;           // 44.7 KB

    cudaFuncSetAttribute(conv3x3<32, true>, cudaFuncAttributeMaxDynamicSharedMemorySize, (int)sm32);
    cudaFuncSetAttribute(conv3x3_out,       cudaFuncAttributeMaxDynamicSharedMemorySize, (int)smo);

    gather_kernel<<<dim3(TT, BB), 128>>>(pitch, onset, tf, x0);

    dim3 grid(FF / 32, TT / 8, BB);
    conv3x3<2,  true><<<grid, 256, sm2 >>>(x0,  W1, b1, a);
    conv3x3<32, true><<<grid, 256, sm32>>>(a,   W2, b2, buf);
    conv3x3<32, true><<<grid, 256, sm32>>>(buf, W3, b3, a);
    conv3x3_out      <<<grid, 256, smo >>>(a,   W4, b4, out);
}